// round 7
// baseline (speedup 1.0000x reference)
#include <cuda_runtime.h>
#include <cuda_bf16.h>
#include <math.h>
#include <stdint.h>

typedef unsigned long long u64;

#define BT 4096     // B*T rows
#define TT 512
#define BB 8
#define EE 512
#define HH 1024
#define H4 4096
#define CC 32000

// ---------------- scratch (device globals; no allocation allowed) ----------
__device__ float g_XG[(size_t)BT * H4];        // gate pre-acts   64 MB
__device__ __align__(16) __nv_bfloat16 g_hh[2][BB * HH];  // h hi, double buf
__device__ __align__(16) __nv_bfloat16 g_hl[2][BB * HH];  // h lo, double buf
__device__ unsigned g_barcnt;                  // grid barrier counter
__device__ __align__(16) __nv_bfloat16 g_Whi[(size_t)CC * HH];  // 64 MB
__device__ __align__(16) __nv_bfloat16 g_Wlo[(size_t)CC * HH];  // 64 MB
__device__ __align__(16) __nv_bfloat16 g_Ahi[(size_t)BT * HH];  //  8 MB
__device__ __align__(16) __nv_bfloat16 g_Alo[(size_t)BT * HH];  //  8 MB

// ---------------- small helpers ---------------------------------------------
__device__ __forceinline__ uint32_t smem_u32(const void* p) {
    uint32_t a;
    asm("{ .reg .u64 t; cvta.to.shared.u64 t, %1; cvt.u32.u64 %0, t; }"
        : "=r"(a) : "l"(p));
    return a;
}
// pack two consecutive-memory elements (e0 low half, e1 high half)
__device__ __forceinline__ uint32_t packbf(float e0, float e1) {
    uint32_t r;
    asm("cvt.rn.bf16x2.f32 %0, %1, %2;" : "=r"(r) : "f"(e1), "f"(e0));
    return r;
}
__device__ __forceinline__ void cpa16(uint32_t s, const void* g) {
    asm volatile("cp.async.cg.shared.global [%0], [%1], 16;" :: "r"(s), "l"(g));
}
#define CPA_COMMIT() asm volatile("cp.async.commit_group;" ::: "memory")
#define CPA_WAIT1()  asm volatile("cp.async.wait_group 1;"  ::: "memory")
#define CPA_WAIT0()  asm volatile("cp.async.wait_group 0;"  ::: "memory")

#define LDSM4(r, a) \
    asm volatile("ldmatrix.sync.aligned.m8n8.x4.shared.b16 {%0,%1,%2,%3}, [%4];" \
        : "=r"((r)[0]), "=r"((r)[1]), "=r"((r)[2]), "=r"((r)[3]) : "r"(a))

__device__ __forceinline__ void mma_bf(float* d, const uint32_t* a, const uint32_t* b) {
    asm volatile(
        "mma.sync.aligned.m16n8k16.row.col.f32.bf16.bf16.f32 "
        "{%0,%1,%2,%3}, {%4,%5,%6,%7}, {%8,%9}, {%0,%1,%2,%3};"
        : "+f"(d[0]), "+f"(d[1]), "+f"(d[2]), "+f"(d[3])
        : "r"(a[0]), "r"(a[1]), "r"(a[2]), "r"(a[3]), "r"(b[0]), "r"(b[1]));
}

// ---------------- hi/lo bf16 split (weights) ---------------------------------
__global__ void split_kernel(const float* __restrict__ src,
                             __nv_bfloat16* __restrict__ hi,
                             __nv_bfloat16* __restrict__ lo, int n4) {
    int i = blockIdx.x * 256 + threadIdx.x;
    if (i >= n4) return;
    float4 v = __ldg((const float4*)src + i);
    float hx = __bfloat162float(__float2bfloat16(v.x));
    float hy = __bfloat162float(__float2bfloat16(v.y));
    float hz = __bfloat162float(__float2bfloat16(v.z));
    float hw = __bfloat162float(__float2bfloat16(v.w));
    uint2 H, L;
    H.x = packbf(hx, hy);         H.y = packbf(hz, hw);
    L.x = packbf(v.x - hx, v.y - hy);
    L.y = packbf(v.z - hz, v.w - hw);
    ((uint2*)hi)[i] = H;
    ((uint2*)lo)[i] = L;
}

// embedding gather -> split bf16 directly into A arrays (K = EE)
__global__ void embed_kernel(const int* __restrict__ x, const float* __restrict__ emb) {
    int row = blockIdx.x;
    int id = __ldg(&x[row]);
    int i = threadIdx.x;                  // 128 threads = EE/4 float4s
    float4 v = __ldg((const float4*)(emb + (size_t)id * EE) + i);
    float hx = __bfloat162float(__float2bfloat16(v.x));
    float hy = __bfloat162float(__float2bfloat16(v.y));
    float hz = __bfloat162float(__float2bfloat16(v.z));
    float hw = __bfloat162float(__float2bfloat16(v.w));
    uint2 H, L;
    H.x = packbf(hx, hy);         H.y = packbf(hz, hw);
    L.x = packbf(v.x - hx, v.y - hy);
    L.y = packbf(v.z - hz, v.w - hw);
    size_t idx = (size_t)row * (EE / 4) + i;
    ((uint2*)g_Ahi)[idx] = H;
    ((uint2*)g_Alo)[idx] = L;
}

// ---------------- bf16 split-MMA GEMM: CTA 128x256, warp tile 64x64 ---------
// C[M,N] = A[M,K] @ W[N,K]^T + b1 (+ b2) via D += Ah*Wh + Ah*Wl + Al*Wh.
// BK=32, 256 threads (8 warps = 2m x 4n), cp.async 2-stage pipeline,
// 80B-padded smem rows. Stage rows: [0,128)=Ahi, [128,256)=Alo,
// [256,512)=Whi, [512,768)=Wlo.
#define SSZ (768 * 80)          // 61440 B per stage
#define GSMEM (2 * SSZ)         // 122880 B

__device__ __forceinline__ void ld_stage(uint32_t sb, int s,
    const __nv_bfloat16* __restrict__ Ah, const __nv_bfloat16* __restrict__ Al,
    const __nv_bfloat16* __restrict__ Wh, const __nv_bfloat16* __restrict__ Wl,
    int m0, int n0, int K, int k0, int tid)
{
    const uint32_t base = sb + (uint32_t)s * SSZ;
#pragma unroll
    for (int i = tid; i < 3072; i += 256) {
        const int rr = i >> 2;           // 0..767
        const int c  = (i & 3) << 4;     // byte offset within 64B row data
        const __nv_bfloat16* gp;
        if (rr < 128)      gp = Ah + (size_t)(m0 + rr) * K;
        else if (rr < 256) gp = Al + (size_t)(m0 + rr - 128) * K;
        else if (rr < 512) gp = Wh + (size_t)(n0 + rr - 256) * K;
        else               gp = Wl + (size_t)(n0 + rr - 512) * K;
        cpa16(base + rr * 80 + c, gp + k0 + (c >> 1));
    }
}

__device__ __forceinline__ void comp_stage(uint32_t sb, int s, int lane,
                                           int wm, int wn, float (*d)[8][4])
{
    const uint32_t base = sb + (uint32_t)s * SSZ;
    const uint32_t aoff = (lane & 15) * 80 + ((lane >> 4) << 4);
    const uint32_t boff = ((((lane >> 4) << 3) + (lane & 7)) * 80) + (((lane >> 3) & 1) << 4);
#pragma unroll
    for (int ks = 0; ks < 2; ks++) {
        const uint32_t kb = ks << 5;
        uint32_t ah[4][4], al[4][4], bh[4][4], bl[4][4];
#pragma unroll
        for (int mt = 0; mt < 4; mt++) {
            uint32_t a = base + (wm + mt * 16) * 80 + aoff + kb;
            LDSM4(ah[mt], a);
            LDSM4(al[mt], a + 128 * 80);
        }
#pragma unroll
        for (int g = 0; g < 4; g++) {
            uint32_t a = base + 256 * 80 + (wn + g * 16) * 80 + boff + kb;
            LDSM4(bh[g], a);
            LDSM4(bl[g], a + 256 * 80);
        }
#pragma unroll
        for (int mt = 0; mt < 4; mt++)
#pragma unroll
            for (int nt = 0; nt < 8; nt++) {
                const uint32_t* ph = &bh[nt >> 1][(nt & 1) << 1];
                const uint32_t* pl = &bl[nt >> 1][(nt & 1) << 1];
                mma_bf(d[mt][nt], ah[mt], ph);
                mma_bf(d[mt][nt], ah[mt], pl);
                mma_bf(d[mt][nt], al[mt], ph);
            }
    }
}

__global__ void __launch_bounds__(256, 1) mma_gemm(
    const __nv_bfloat16* __restrict__ Ahi, const __nv_bfloat16* __restrict__ Alo,
    const __nv_bfloat16* __restrict__ Whi, const __nv_bfloat16* __restrict__ Wlo,
    const float* __restrict__ b1, const float* __restrict__ b2,
    float* __restrict__ C, int M, int N, int K)
{
    extern __shared__ char sm[];
    const uint32_t sb = smem_u32(sm);
    const int tid = threadIdx.x, lane = tid & 31, wid = tid >> 5;
    const int m0 = blockIdx.x << 7, n0 = blockIdx.y << 8;
    const int wm = (wid >> 2) << 6, wn = (wid & 3) << 6;

    float d[4][8][4];
#pragma unroll
    for (int i = 0; i < 4; i++)
#pragma unroll
        for (int j = 0; j < 8; j++)
#pragma unroll
            for (int k = 0; k < 4; k++) d[i][j][k] = 0.f;

    const int KT = K >> 5;
    ld_stage(sb, 0, Ahi, Alo, Whi, Wlo, m0, n0, K, 0, tid);
    CPA_COMMIT();
    for (int kt = 0; kt < KT; kt++) {
        if (kt + 1 < KT) {
            ld_stage(sb, (kt + 1) & 1, Ahi, Alo, Whi, Wlo, m0, n0, K, (kt + 1) << 5, tid);
            CPA_COMMIT();
            CPA_WAIT1();
        } else {
            CPA_WAIT0();
        }
        __syncthreads();
        comp_stage(sb, kt & 1, lane, wm, wn, d);
        __syncthreads();
    }

#pragma unroll
    for (int mt = 0; mt < 4; mt++) {
        const int row0 = m0 + wm + mt * 16 + (lane >> 2);
#pragma unroll
        for (int nt = 0; nt < 8; nt++) {
            const int col = n0 + wn + nt * 8 + ((lane & 3) << 1);
            float bb0 = __ldg(&b1[col]);
            float bb1 = __ldg(&b1[col + 1]);
            if (b2) { bb0 += __ldg(&b2[col]); bb1 += __ldg(&b2[col + 1]); }
            float2 v0 = { d[mt][nt][0] + bb0, d[mt][nt][1] + bb1 };
            float2 v1 = { d[mt][nt][2] + bb0, d[mt][nt][3] + bb1 };
            *(float2*)&C[(size_t)row0 * N + col]       = v0;
            *(float2*)&C[(size_t)(row0 + 8) * N + col] = v1;
        }
    }
}

// ---------------- LSTM recurrence: persistent tensor-core kernel -----------
// (see R6 notes) h output written directly as bf16 hi/lo in GEMM-A layout.
#define HS_STRIDE_B 2064          // bytes per h row (1032 bf16; banks shift 4)
#define PS_STRIDE_W 272           // floats per warp partial row
#define LSTM_SMEM (16 * HS_STRIDE_B + 16 * PS_STRIDE_W * 4)   // 50432 B

__device__ __forceinline__ float sigmoidf_(float x) { return 1.f / (1.f + expf(-x)); }

__global__ void __launch_bounds__(512, 1) lstm_kernel(
    const float* __restrict__ Whh,          // [4096, 1024]
    const float* __restrict__ XG,           // [(b*T+t), 4096] pre-acts + biases
    __nv_bfloat16* __restrict__ Hhi,        // [(b*T+t), 1024] h hi out
    __nv_bfloat16* __restrict__ Hlo)        // [(b*T+t), 1024] h lo out
{
    extern __shared__ char dsm[];
    char*  hsb = dsm;                          // [16 rows][2064 B] bf16 h hi/lo
    float* ps  = (float*)(dsm + 16 * HS_STRIDE_B);  // [16 warps][272]
    __shared__ float gates[32][8];
    __shared__ float c_s[64];

    const int tid  = threadIdx.x;
    const int blk  = blockIdx.x;
    const int lane = tid & 31;
    const int w    = tid >> 5;        // warp = k-chunk 0..15
    const int kb   = w << 6;          // k base

    // ---- load Whh fragments (hi/lo bf16) into registers, once -------------
    uint32_t bh0[4][4], bh1[4][4], bl0[4][4], bl1[4][4];
#pragma unroll
    for (int nt = 0; nt < 4; nt++) {
        const float* wrow = Whh + (size_t)((nt << 10) + (blk << 3) + (lane >> 2)) * HH
                          + kb + ((lane & 3) << 1);
#pragma unroll
        for (int ks = 0; ks < 4; ks++) {
            float2 v0 = *(const float2*)(wrow + ks * 16);
            float2 v8 = *(const float2*)(wrow + ks * 16 + 8);
            float h0 = __bfloat162float(__float2bfloat16(v0.x));
            float h1 = __bfloat162float(__float2bfloat16(v0.y));
            float h8 = __bfloat162float(__float2bfloat16(v8.x));
            float h9 = __bfloat162float(__float2bfloat16(v8.y));
            bh0[nt][ks] = packbf(h0, h1);
            bh1[nt][ks] = packbf(h8, h9);
            bl0[nt][ks] = packbf(v0.x - h0, v0.y - h1);
            bl1[nt][ks] = packbf(v8.x - h8, v8.y - h9);
        }
    }
    if (tid < 64) c_s[tid] = 0.f;

    const char* arow_hi = hsb + (lane >> 2) * HS_STRIDE_B + (kb << 1) + ((lane & 3) << 2);
    const char* arow_lo = arow_hi + 8 * HS_STRIDE_B;
    float* psw = ps + w * PS_STRIDE_W + (lane >> 2) * 34 + ((lane & 3) << 1);

    const int rb = tid >> 5, rn = tid & 31;
    const float* psr = ps + rb * 34 + rn;
    const int grow_red = ((rn >> 3) << 10) + (blk << 3) + (rn & 7);

    unsigned target = 0;
    for (int t = 0; t < TT; t++) {
        const int cur = t & 1;
        float gin = 0.f;
        if (tid < 256)
            gin = __ldg(&XG[(size_t)((rb << 9) + t) * H4 + grow_red]);
        {
            const uint4* shi = (const uint4*)g_hh[cur];
            const uint4* slo = (const uint4*)g_hl[cur];
#pragma unroll
            for (int i = tid; i < 1024; i += 512) {
                int row = i >> 7, c = (i & 127) << 4;
                *(uint4*)(hsb + row * HS_STRIDE_B + c)       = __ldcg(&shi[i]);
                *(uint4*)(hsb + (row + 8) * HS_STRIDE_B + c) = __ldcg(&slo[i]);
            }
        }
        __syncthreads();

        float d[4][4];
#pragma unroll
        for (int nt = 0; nt < 4; nt++)
#pragma unroll
            for (int j = 0; j < 4; j++) d[nt][j] = 0.f;
#pragma unroll
        for (int ks = 0; ks < 4; ks++) {
            uint32_t a[4];
            a[0] = *(const uint32_t*)(arow_hi + ks * 32);
            a[1] = *(const uint32_t*)(arow_lo + ks * 32);
            a[2] = *(const uint32_t*)(arow_hi + ks * 32 + 16);
            a[3] = *(const uint32_t*)(arow_lo + ks * 32 + 16);
#pragma unroll
            for (int nt = 0; nt < 4; nt++) {
                uint32_t Bh[2] = { bh0[nt][ks], bh1[nt][ks] };
                uint32_t Bl[2] = { bl0[nt][ks], bl1[nt][ks] };
                mma_bf(d[nt], a, Bh);
                mma_bf(d[nt], a, Bl);
            }
        }
#pragma unroll
        for (int nt = 0; nt < 4; nt++) {
            float2 v = { d[nt][0] + d[nt][2], d[nt][1] + d[nt][3] };
            *(float2*)(psw + nt * 8) = v;
        }
        __syncthreads();

        if (tid < 256) {
            float s = gin;
#pragma unroll
            for (int k2 = 0; k2 < 16; k2++)
                s += psr[k2 * PS_STRIDE_W];
            gates[rn][rb] = ((rn >> 3) == 2) ? tanhf(s) : sigmoidf_(s);
        }
        __syncthreads();

        if (tid < 64) {    // cell update: unit uu, batch bu (plain stores)
            int uu = tid >> 3, bu = tid & 7;
            float c = gates[8 + uu][bu] * c_s[tid] + gates[uu][bu] * gates[16 + uu][bu];
            c_s[tid] = c;
            float h = gates[24 + uu][bu] * tanhf(c);
            int j = (blk << 3) + uu;
            __nv_bfloat16 hh = __float2bfloat16(h);
            __nv_bfloat16 hl = __float2bfloat16(h - __bfloat162float(hh));
            g_hh[cur ^ 1][bu * HH + j] = hh;
            g_hl[cur ^ 1][bu * HH + j] = hl;
            size_t orow = (size_t)((bu << 9) + t) * HH + j;
            Hhi[orow] = hh;
            Hlo[orow] = hl;
        }

        if (t != TT - 1) {  // grid barrier: one cumulative fence by tid0
            target += 128;
            __syncthreads();
            if (tid == 0) {
                __threadfence();                     // release (cumulative)
                atomicAdd(&g_barcnt, 1u);            // RED arrival
                while (*(volatile unsigned*)&g_barcnt < target) { }
                __threadfence();                     // acquire
            }
            __syncthreads();
        }
    }
}

__global__ void reset_kernel() {
    unsigned t = blockIdx.x * blockDim.x + threadIdx.x;
    if (t == 0) g_barcnt = 0u;
    if (t < (BB * HH) / 2) {
        ((uint32_t*)g_hh[0])[t] = 0u;
        ((uint32_t*)g_hl[0])[t] = 0u;
    }
}

// ---------------- launch ----------------------------------------------------
extern "C" void kernel_launch(void* const* d_in, const int* in_sizes, int n_in,
                              void* d_out, int out_size)
{
    const int*   x    = (const int*)  d_in[0];
    const float* emb  = (const float*)d_in[1];
    const float* Wih0 = (const float*)d_in[2];
    const float* Whh0 = (const float*)d_in[3];
    const float* bih0 = (const float*)d_in[4];
    const float* bhh0 = (const float*)d_in[5];
    const float* Wih1 = (const float*)d_in[6];
    const float* Whh1 = (const float*)d_in[7];
    const float* bih1 = (const float*)d_in[8];
    const float* bhh1 = (const float*)d_in[9];
    const float* Wout = (const float*)d_in[10];
    const float* bout = (const float*)d_in[11];
    float* out = (float*)d_out;

    float *pXG;
    __nv_bfloat16 *pWhi, *pWlo, *pAhi, *pAlo;
    cudaGetSymbolAddress((void**)&pXG, g_XG);
    cudaGetSymbolAddress((void**)&pWhi, g_Whi);
    cudaGetSymbolAddress((void**)&pWlo, g_Wlo);
    cudaGetSymbolAddress((void**)&pAhi, g_Ahi);
    cudaGetSymbolAddress((void**)&pAlo, g_Alo);

    cudaFuncSetAttribute(lstm_kernel,
                         cudaFuncAttributeMaxDynamicSharedMemorySize, LSTM_SMEM);
    cudaFuncSetAttribute(mma_gemm,
                         cudaFuncAttributeMaxDynamicSharedMemorySize, GSMEM);

    // 1) embedding (writes split bf16 X0 into Ahi/Alo)
    embed_kernel<<<BT, 128>>>(x, emb);
    // 2) layer0 input GEMM: XG = X0 @ Wih0^T + bih0 + bhh0
    {
        int n4 = (H4 * EE) / 4;
        split_kernel<<<(n4 + 255) / 256, 256>>>(Wih0, pWhi, pWlo, n4);
        mma_gemm<<<dim3(BT / 128, H4 / 256), 256, GSMEM>>>(
            pAhi, pAlo, pWhi, pWlo, bih0, bhh0, pXG, BT, H4, EE);
    }
    // 3) layer0 recurrence (writes split H0 into Ahi/Alo)
    reset_kernel<<<32, 256>>>();
    lstm_kernel<<<128, 512, LSTM_SMEM>>>(Whh0, pXG, pAhi, pAlo);
    // 4) layer1 input GEMM: XG = H0 @ Wih1^T + bih1 + bhh1
    {
        int n4w = (H4 * HH) / 4;
        split_kernel<<<(n4w + 255) / 256, 256>>>(Wih1, pWhi, pWlo, n4w);
        mma_gemm<<<dim3(BT / 128, H4 / 256), 256, GSMEM>>>(
            pAhi, pAlo, pWhi, pWlo, bih1, bhh1, pXG, BT, H4, HH);
    }
    // 5) layer1 recurrence (writes split H1 into Ahi/Alo)
    reset_kernel<<<32, 256>>>();
    lstm_kernel<<<128, 512, LSTM_SMEM>>>(Whh1, pXG, pAhi, pAlo);
    // 6) output GEMM: logits = H1 @ Wout^T + bout
    {
        int n4w = (int)(((size_t)CC * HH) / 4);
        split_kernel<<<(n4w + 255) / 256, 256>>>(Wout, pWhi, pWlo, n4w);
        mma_gemm<<<dim3(BT / 128, CC / 256), 256, GSMEM>>>(
            pAhi, pAlo, pWhi, pWlo, bout, nullptr, out, BT, CC, HH);
    }
}

// round 8
// speedup vs baseline: 1.0478x; 1.0478x over previous
#include <cuda_runtime.h>
#include <cuda_bf16.h>
#include <math.h>
#include <stdint.h>

typedef unsigned long long u64;

#define BT 4096     // B*T rows
#define TT 512
#define BB 8
#define EE 512
#define HH 1024
#define H4 4096
#define CC 32000

// ---------------- scratch (device globals; no allocation allowed) ----------
__device__ float g_XG[(size_t)BT * H4];        // gate pre-acts   64 MB
__device__ __align__(16) __nv_bfloat16 g_hh[2][BB * HH];  // h hi, double buf
__device__ __align__(16) __nv_bfloat16 g_hl[2][BB * HH];  // h lo, double buf
__device__ unsigned g_barcnt;                  // grid barrier counter
__device__ __align__(16) __nv_bfloat16 g_Whi[(size_t)CC * HH];  // 64 MB
__device__ __align__(16) __nv_bfloat16 g_Wlo[(size_t)CC * HH];  // 64 MB
__device__ __align__(16) __nv_bfloat16 g_Ahi[(size_t)BT * HH];  //  8 MB
__device__ __align__(16) __nv_bfloat16 g_Alo[(size_t)BT * HH];  //  8 MB

// ---------------- small helpers ---------------------------------------------
__device__ __forceinline__ uint32_t smem_u32(const void* p) {
    uint32_t a;
    asm("{ .reg .u64 t; cvta.to.shared.u64 t, %1; cvt.u32.u64 %0, t; }"
        : "=r"(a) : "l"(p));
    return a;
}
// pack two consecutive-memory elements (e0 low half, e1 high half)
__device__ __forceinline__ uint32_t packbf(float e0, float e1) {
    uint32_t r;
    asm("cvt.rn.bf16x2.f32 %0, %1, %2;" : "=r"(r) : "f"(e1), "f"(e0));
    return r;
}
__device__ __forceinline__ void cpa16(uint32_t s, const void* g) {
    asm volatile("cp.async.cg.shared.global [%0], [%1], 16;" :: "r"(s), "l"(g));
}
#define CPA_COMMIT() asm volatile("cp.async.commit_group;" ::: "memory")
#define CPA_WAIT1()  asm volatile("cp.async.wait_group 1;"  ::: "memory")
#define CPA_WAIT0()  asm volatile("cp.async.wait_group 0;"  ::: "memory")

#define LDSM4(r, a) \
    asm volatile("ldmatrix.sync.aligned.m8n8.x4.shared.b16 {%0,%1,%2,%3}, [%4];" \
        : "=r"((r)[0]), "=r"((r)[1]), "=r"((r)[2]), "=r"((r)[3]) : "r"(a))

__device__ __forceinline__ void mma_bf(float* d, const uint32_t* a, const uint32_t* b) {
    asm volatile(
        "mma.sync.aligned.m16n8k16.row.col.f32.bf16.bf16.f32 "
        "{%0,%1,%2,%3}, {%4,%5,%6,%7}, {%8,%9}, {%0,%1,%2,%3};"
        : "+f"(d[0]), "+f"(d[1]), "+f"(d[2]), "+f"(d[3])
        : "r"(a[0]), "r"(a[1]), "r"(a[2]), "r"(a[3]), "r"(b[0]), "r"(b[1]));
}

// ---------------- hi/lo bf16 split (weights) ---------------------------------
__global__ void split_kernel(const float* __restrict__ src,
                             __nv_bfloat16* __restrict__ hi,
                             __nv_bfloat16* __restrict__ lo, int n4) {
    int i = blockIdx.x * 256 + threadIdx.x;
    if (i >= n4) return;
    float4 v = __ldg((const float4*)src + i);
    float hx = __bfloat162float(__float2bfloat16(v.x));
    float hy = __bfloat162float(__float2bfloat16(v.y));
    float hz = __bfloat162float(__float2bfloat16(v.z));
    float hw = __bfloat162float(__float2bfloat16(v.w));
    uint2 H, L;
    H.x = packbf(hx, hy);         H.y = packbf(hz, hw);
    L.x = packbf(v.x - hx, v.y - hy);
    L.y = packbf(v.z - hz, v.w - hw);
    ((uint2*)hi)[i] = H;
    ((uint2*)lo)[i] = L;
}

// embedding gather -> split bf16 directly into A arrays (K = EE)
__global__ void embed_kernel(const int* __restrict__ x, const float* __restrict__ emb) {
    int row = blockIdx.x;
    int id = __ldg(&x[row]);
    int i = threadIdx.x;                  // 128 threads = EE/4 float4s
    float4 v = __ldg((const float4*)(emb + (size_t)id * EE) + i);
    float hx = __bfloat162float(__float2bfloat16(v.x));
    float hy = __bfloat162float(__float2bfloat16(v.y));
    float hz = __bfloat162float(__float2bfloat16(v.z));
    float hw = __bfloat162float(__float2bfloat16(v.w));
    uint2 H, L;
    H.x = packbf(hx, hy);         H.y = packbf(hz, hw);
    L.x = packbf(v.x - hx, v.y - hy);
    L.y = packbf(v.z - hz, v.w - hw);
    size_t idx = (size_t)row * (EE / 4) + i;
    ((uint2*)g_Ahi)[idx] = H;
    ((uint2*)g_Alo)[idx] = L;
}

// ---------------- bf16 split-MMA GEMM (R6 config: CTA 128x128, occ 2) -------
// C[M,N] = A[M,K] @ W[N,K]^T + b1 (+ b2) via D += Ah*Wh + Ah*Wl + Al*Wh.
// BK=32, 256 threads (8 warps, warp tile 64x32), cp.async 2-stage pipeline,
// 80B-padded smem rows; GSMEM=81920 -> 2 CTAs/SM co-resident.
#define RS 40                   // smem row stride in bf16 (80 bytes)
#define SSZ (128 * RS * 2)      // 10240 B: one array, one stage
#define GSMEM (8 * SSZ)         // 4 arrays x 2 stages = 81920 B

__device__ __forceinline__ void ld_stage(uint32_t sb, int s,
    const __nv_bfloat16* __restrict__ Ah, const __nv_bfloat16* __restrict__ Al,
    const __nv_bfloat16* __restrict__ Wh, const __nv_bfloat16* __restrict__ Wl,
    int m0, int n0, int K, int k0, int tid)
{
    const int r  = tid >> 2;
    const int kb = (tid & 3) << 3;
    const uint32_t so = sb + (uint32_t)s * SSZ + r * 80 + (kb << 1);
    const size_t gA = (size_t)(m0 + r) * K + k0 + kb;
    const size_t gW = (size_t)(n0 + r) * K + k0 + kb;
    const size_t g64 = (size_t)64 * K;
    cpa16(so,                  Ah + gA);
    cpa16(so + 64 * 80,        Ah + gA + g64);
    cpa16(so + 2 * SSZ,            Al + gA);
    cpa16(so + 2 * SSZ + 64 * 80,  Al + gA + g64);
    cpa16(so + 4 * SSZ,            Wh + gW);
    cpa16(so + 4 * SSZ + 64 * 80,  Wh + gW + g64);
    cpa16(so + 6 * SSZ,            Wl + gW);
    cpa16(so + 6 * SSZ + 64 * 80,  Wl + gW + g64);
}

__device__ __forceinline__ void comp_stage(uint32_t sb, int s, int lane,
                                           int wm, int wn, float (*d)[4][4])
{
    const uint32_t base = sb + (uint32_t)s * SSZ;
    const uint32_t aoff = (lane & 15) * 80 + ((lane >> 4) << 4);
    const uint32_t boff = ((((lane >> 4) << 3) + (lane & 7)) * 80) + (((lane >> 3) & 1) << 4);
#pragma unroll
    for (int ks = 0; ks < 2; ks++) {
        const uint32_t kb = ks << 5;
        uint32_t ah[4][4], al[4][4], bh[2][4], bl[2][4];
#pragma unroll
        for (int mt = 0; mt < 4; mt++) {
            uint32_t a = base + (wm + mt * 16) * 80 + aoff + kb;
            LDSM4(ah[mt], a);
            LDSM4(al[mt], a + 2 * SSZ);
        }
#pragma unroll
        for (int g = 0; g < 2; g++) {
            uint32_t a = base + 4 * SSZ + (wn + g * 16) * 80 + boff + kb;
            LDSM4(bh[g], a);
            LDSM4(bl[g], a + 2 * SSZ);
        }
#pragma unroll
        for (int mt = 0; mt < 4; mt++)
#pragma unroll
            for (int nt = 0; nt < 4; nt++) {
                const uint32_t* ph = &bh[nt >> 1][(nt & 1) << 1];
                const uint32_t* pl = &bl[nt >> 1][(nt & 1) << 1];
                mma_bf(d[mt][nt], ah[mt], ph);
                mma_bf(d[mt][nt], ah[mt], pl);
                mma_bf(d[mt][nt], al[mt], ph);
            }
    }
}

__global__ void __launch_bounds__(256) mma_gemm(
    const __nv_bfloat16* __restrict__ Ahi, const __nv_bfloat16* __restrict__ Alo,
    const __nv_bfloat16* __restrict__ Whi, const __nv_bfloat16* __restrict__ Wlo,
    const float* __restrict__ b1, const float* __restrict__ b2,
    float* __restrict__ C, int M, int N, int K)
{
    extern __shared__ char sm[];
    const uint32_t sb = smem_u32(sm);
    const int tid = threadIdx.x, lane = tid & 31, wid = tid >> 5;
    const int m0 = blockIdx.x << 7, n0 = blockIdx.y << 7;
    const int wm = (wid >> 2) << 6, wn = (wid & 3) << 5;

    float d[4][4][4];
#pragma unroll
    for (int i = 0; i < 4; i++)
#pragma unroll
        for (int j = 0; j < 4; j++)
#pragma unroll
            for (int k = 0; k < 4; k++) d[i][j][k] = 0.f;

    const int KT = K >> 5;
    ld_stage(sb, 0, Ahi, Alo, Whi, Wlo, m0, n0, K, 0, tid);
    CPA_COMMIT();
    for (int kt = 0; kt < KT; kt++) {
        if (kt + 1 < KT) {
            ld_stage(sb, (kt + 1) & 1, Ahi, Alo, Whi, Wlo, m0, n0, K, (kt + 1) << 5, tid);
            CPA_COMMIT();
            CPA_WAIT1();
        } else {
            CPA_WAIT0();
        }
        __syncthreads();
        comp_stage(sb, kt & 1, lane, wm, wn, d);
        __syncthreads();
    }

#pragma unroll
    for (int mt = 0; mt < 4; mt++) {
        const int row0 = m0 + wm + mt * 16 + (lane >> 2);
#pragma unroll
        for (int nt = 0; nt < 4; nt++) {
            const int col = n0 + wn + nt * 8 + ((lane & 3) << 1);
            float bb0 = __ldg(&b1[col]);
            float bb1 = __ldg(&b1[col + 1]);
            if (b2) { bb0 += __ldg(&b2[col]); bb1 += __ldg(&b2[col + 1]); }
            float2 v0 = { d[mt][nt][0] + bb0, d[mt][nt][1] + bb1 };
            float2 v1 = { d[mt][nt][2] + bb0, d[mt][nt][3] + bb1 };
            *(float2*)&C[(size_t)row0 * N + col]       = v0;
            *(float2*)&C[(size_t)(row0 + 8) * N + col] = v1;
        }
    }
}

// ---------------- LSTM recurrence: persistent tensor-core kernel -----------
// (see R6 notes) h output written directly as bf16 hi/lo in GEMM-A layout.
#define HS_STRIDE_B 2064          // bytes per h row (1032 bf16; banks shift 4)
#define PS_STRIDE_W 272           // floats per warp partial row
#define LSTM_SMEM (16 * HS_STRIDE_B + 16 * PS_STRIDE_W * 4)   // 50432 B

__device__ __forceinline__ float sigmoidf_(float x) { return 1.f / (1.f + expf(-x)); }

__global__ void __launch_bounds__(512, 1) lstm_kernel(
    const float* __restrict__ Whh,          // [4096, 1024]
    const float* __restrict__ XG,           // [(b*T+t), 4096] pre-acts + biases
    __nv_bfloat16* __restrict__ Hhi,        // [(b*T+t), 1024] h hi out
    __nv_bfloat16* __restrict__ Hlo)        // [(b*T+t), 1024] h lo out
{
    extern __shared__ char dsm[];
    char*  hsb = dsm;                          // [16 rows][2064 B] bf16 h hi/lo
    float* ps  = (float*)(dsm + 16 * HS_STRIDE_B);  // [16 warps][272]
    __shared__ float gates[32][8];
    __shared__ float c_s[64];

    const int tid  = threadIdx.x;
    const int blk  = blockIdx.x;
    const int lane = tid & 31;
    const int w    = tid >> 5;        // warp = k-chunk 0..15
    const int kb   = w << 6;          // k base

    // ---- load Whh fragments (hi/lo bf16) into registers, once -------------
    uint32_t bh0[4][4], bh1[4][4], bl0[4][4], bl1[4][4];
#pragma unroll
    for (int nt = 0; nt < 4; nt++) {
        const float* wrow = Whh + (size_t)((nt << 10) + (blk << 3) + (lane >> 2)) * HH
                          + kb + ((lane & 3) << 1);
#pragma unroll
        for (int ks = 0; ks < 4; ks++) {
            float2 v0 = *(const float2*)(wrow + ks * 16);
            float2 v8 = *(const float2*)(wrow + ks * 16 + 8);
            float h0 = __bfloat162float(__float2bfloat16(v0.x));
            float h1 = __bfloat162float(__float2bfloat16(v0.y));
            float h8 = __bfloat162float(__float2bfloat16(v8.x));
            float h9 = __bfloat162float(__float2bfloat16(v8.y));
            bh0[nt][ks] = packbf(h0, h1);
            bh1[nt][ks] = packbf(h8, h9);
            bl0[nt][ks] = packbf(v0.x - h0, v0.y - h1);
            bl1[nt][ks] = packbf(v8.x - h8, v8.y - h9);
        }
    }
    if (tid < 64) c_s[tid] = 0.f;

    const char* arow_hi = hsb + (lane >> 2) * HS_STRIDE_B + (kb << 1) + ((lane & 3) << 2);
    const char* arow_lo = arow_hi + 8 * HS_STRIDE_B;
    float* psw = ps + w * PS_STRIDE_W + (lane >> 2) * 34 + ((lane & 3) << 1);

    const int rb = tid >> 5, rn = tid & 31;
    const float* psr = ps + rb * 34 + rn;
    const int grow_red = ((rn >> 3) << 10) + (blk << 3) + (rn & 7);

    unsigned target = 0;
    for (int t = 0; t < TT; t++) {
        const int cur = t & 1;
        float gin = 0.f;
        if (tid < 256)
            gin = __ldg(&XG[(size_t)((rb << 9) + t) * H4 + grow_red]);
        {
            const uint4* shi = (const uint4*)g_hh[cur];
            const uint4* slo = (const uint4*)g_hl[cur];
#pragma unroll
            for (int i = tid; i < 1024; i += 512) {
                int row = i >> 7, c = (i & 127) << 4;
                *(uint4*)(hsb + row * HS_STRIDE_B + c)       = __ldcg(&shi[i]);
                *(uint4*)(hsb + (row + 8) * HS_STRIDE_B + c) = __ldcg(&slo[i]);
            }
        }
        __syncthreads();

        float d[4][4];
#pragma unroll
        for (int nt = 0; nt < 4; nt++)
#pragma unroll
            for (int j = 0; j < 4; j++) d[nt][j] = 0.f;
#pragma unroll
        for (int ks = 0; ks < 4; ks++) {
            uint32_t a[4];
            a[0] = *(const uint32_t*)(arow_hi + ks * 32);
            a[1] = *(const uint32_t*)(arow_lo + ks * 32);
            a[2] = *(const uint32_t*)(arow_hi + ks * 32 + 16);
            a[3] = *(const uint32_t*)(arow_lo + ks * 32 + 16);
#pragma unroll
            for (int nt = 0; nt < 4; nt++) {
                uint32_t Bh[2] = { bh0[nt][ks], bh1[nt][ks] };
                uint32_t Bl[2] = { bl0[nt][ks], bl1[nt][ks] };
                mma_bf(d[nt], a, Bh);
                mma_bf(d[nt], a, Bl);
            }
        }
#pragma unroll
        for (int nt = 0; nt < 4; nt++) {
            float2 v = { d[nt][0] + d[nt][2], d[nt][1] + d[nt][3] };
            *(float2*)(psw + nt * 8) = v;
        }
        __syncthreads();

        if (tid < 256) {
            float s = gin;
#pragma unroll
            for (int k2 = 0; k2 < 16; k2++)
                s += psr[k2 * PS_STRIDE_W];
            gates[rn][rb] = ((rn >> 3) == 2) ? tanhf(s) : sigmoidf_(s);
        }
        __syncthreads();

        if (tid < 64) {    // cell update: unit uu, batch bu (plain stores)
            int uu = tid >> 3, bu = tid & 7;
            float c = gates[8 + uu][bu] * c_s[tid] + gates[uu][bu] * gates[16 + uu][bu];
            c_s[tid] = c;
            float h = gates[24 + uu][bu] * tanhf(c);
            int j = (blk << 3) + uu;
            __nv_bfloat16 hh = __float2bfloat16(h);
            __nv_bfloat16 hl = __float2bfloat16(h - __bfloat162float(hh));
            g_hh[cur ^ 1][bu * HH + j] = hh;
            g_hl[cur ^ 1][bu * HH + j] = hl;
            size_t orow = (size_t)((bu << 9) + t) * HH + j;
            Hhi[orow] = hh;
            Hlo[orow] = hl;
        }

        if (t != TT - 1) {  // grid barrier: one cumulative fence by tid0
            target += 128;
            __syncthreads();
            if (tid == 0) {
                __threadfence();                     // release (cumulative)
                atomicAdd(&g_barcnt, 1u);            // RED arrival
                while (*(volatile unsigned*)&g_barcnt < target) { }
                __threadfence();                     // acquire
            }
            __syncthreads();
        }
    }
}

__global__ void reset_kernel() {
    unsigned t = blockIdx.x * blockDim.x + threadIdx.x;
    if (t == 0) g_barcnt = 0u;
    if (t < (BB * HH) / 2) {
        ((uint32_t*)g_hh[0])[t] = 0u;
        ((uint32_t*)g_hl[0])[t] = 0u;
    }
}

// ---------------- launch ----------------------------------------------------
extern "C" void kernel_launch(void* const* d_in, const int* in_sizes, int n_in,
                              void* d_out, int out_size)
{
    const int*   x    = (const int*)  d_in[0];
    const float* emb  = (const float*)d_in[1];
    const float* Wih0 = (const float*)d_in[2];
    const float* Whh0 = (const float*)d_in[3];
    const float* bih0 = (const float*)d_in[4];
    const float* bhh0 = (const float*)d_in[5];
    const float* Wih1 = (const float*)d_in[6];
    const float* Whh1 = (const float*)d_in[7];
    const float* bih1 = (const float*)d_in[8];
    const float* bhh1 = (const float*)d_in[9];
    const float* Wout = (const float*)d_in[10];
    const float* bout = (const float*)d_in[11];
    float* out = (float*)d_out;

    float *pXG;
    __nv_bfloat16 *pWhi, *pWlo, *pAhi, *pAlo;
    cudaGetSymbolAddress((void**)&pXG, g_XG);
    cudaGetSymbolAddress((void**)&pWhi, g_Whi);
    cudaGetSymbolAddress((void**)&pWlo, g_Wlo);
    cudaGetSymbolAddress((void**)&pAhi, g_Ahi);
    cudaGetSymbolAddress((void**)&pAlo, g_Alo);

    cudaFuncSetAttribute(lstm_kernel,
                         cudaFuncAttributeMaxDynamicSharedMemorySize, LSTM_SMEM);
    cudaFuncSetAttribute(mma_gemm,
                         cudaFuncAttributeMaxDynamicSharedMemorySize, GSMEM);

    // 1) embedding (writes split bf16 X0 into Ahi/Alo)
    embed_kernel<<<BT, 128>>>(x, emb);
    // 2) layer0 input GEMM: XG = X0 @ Wih0^T + bih0 + bhh0
    {
        int n4 = (H4 * EE) / 4;
        split_kernel<<<(n4 + 255) / 256, 256>>>(Wih0, pWhi, pWlo, n4);
        mma_gemm<<<dim3(BT / 128, H4 / 128), 256, GSMEM>>>(
            pAhi, pAlo, pWhi, pWlo, bih0, bhh0, pXG, BT, H4, EE);
    }
    // 3) layer0 recurrence (writes split H0 into Ahi/Alo)
    reset_kernel<<<32, 256>>>();
    lstm_kernel<<<128, 512, LSTM_SMEM>>>(Whh0, pXG, pAhi, pAlo);
    // 4) layer1 input GEMM: XG = H0 @ Wih1^T + bih1 + bhh1
    {
        int n4w = (H4 * HH) / 4;
        split_kernel<<<(n4w + 255) / 256, 256>>>(Wih1, pWhi, pWlo, n4w);
        mma_gemm<<<dim3(BT / 128, H4 / 128), 256, GSMEM>>>(
            pAhi, pAlo, pWhi, pWlo, bih1, bhh1, pXG, BT, H4, HH);
    }
    // 5) layer1 recurrence (writes split H1 into Ahi/Alo)
    reset_kernel<<<32, 256>>>();
    lstm_kernel<<<128, 512, LSTM_SMEM>>>(Whh1, pXG, pAhi, pAlo);
    // 6) output GEMM: logits = H1 @ Wout^T + bout
    {
        int n4w = (int)(((size_t)CC * HH) / 4);
        split_kernel<<<(n4w + 255) / 256, 256>>>(Wout, pWhi, pWlo, n4w);
        mma_gemm<<<dim3(BT / 128, CC / 128), 256, GSMEM>>>(
            pAhi, pAlo, pWhi, pWlo, bout, nullptr, out, BT, CC, HH);
    }
}